// round 5
// baseline (speedup 1.0000x reference)
#include <cuda_runtime.h>
#include <cstdint>

// Problem constants
#define B_ROWS  16384
#define DIM     2048
#define NTOP    8
#define NC      16
#define NB      128          // bottom logit columns
#define NL      136          // logits per row: [0..127]=bottom, [128..135]=top
#define KC      16           // K-chunk
#define MT      128          // rows per CTA
#define NCHUNK  (DIM / KC)   // 128

// Scratch for logits (static __device__ allocation is allowed; runtime alloc is not)
__device__ __align__(16) float g_logits[B_ROWS * NL];

// ---------- f32x2 packed helpers ----------
__device__ __forceinline__ unsigned long long pack_dup(float v) {
    unsigned long long r;
    asm("mov.b64 %0, {%1, %1};" : "=l"(r) : "f"(v));
    return r;
}
__device__ __forceinline__ void fma2(unsigned long long &acc,
                                     unsigned long long a,
                                     unsigned long long b) {
    asm("fma.rn.f32x2 %0, %1, %2, %0;" : "+l"(acc) : "l"(a), "l"(b));
}
__device__ __forceinline__ float lo32(unsigned long long p) {
    return __uint_as_float((unsigned)(p & 0xffffffffull));
}
__device__ __forceinline__ float hi32(unsigned long long p) {
    return __uint_as_float((unsigned)(p >> 32));
}

// ============================================================================
// GEMM: logits[row][j] = X[row] . W[:, j]   (j<128: bottom, j>=128: top)
// 128 CTAs x 256 threads. Thread (tx,ty) computes 8 rows x 8 cols in f32x2
// column-pair accumulators; threads tx<8 additionally compute top col tx.
// ============================================================================
__global__ void __launch_bounds__(256, 1)
hc_gemm_kernel(const float* __restrict__ features,
               const float* __restrict__ top_W,
               const float* __restrict__ bottom_W)
{
    __shared__ float Xs[KC][MT + 4];     // [k][row], stride 132 (conflict padding)
    __shared__ float Ws[KC][NB + 4];     // [k][j],   stride 132
    __shared__ float Wts[KC][NTOP];      // [k][t]

    const int tid  = threadIdx.x;
    const int tx   = tid & 15;           // column group: cols tx*8 .. tx*8+7
    const int ty   = tid >> 4;           // row group:    rows ty*8 .. ty*8+7
    const int row0 = blockIdx.x * MT;

    // f32x2 accumulators: 8 rows x 4 column-pairs (cols 2c2, 2c2+1)
    unsigned long long acc[8][4];
#pragma unroll
    for (int r = 0; r < 8; ++r)
#pragma unroll
        for (int c = 0; c < 4; ++c) acc[r][c] = 0ull;
    float tacc[8];
#pragma unroll
    for (int r = 0; r < 8; ++r) tacc[r] = 0.0f;

    // ---- register prefetch state (2 float4 of X, 2 float4 of W, 1 top scalar)
    float4 px[2], pw[2];
    float  ptw = 0.0f;

    // decode fixed indices for the two prefetch slots
    int xi_row[2], xi_kq[2], wi_d[2], wi_t[2], wi_cq[2];
#pragma unroll
    for (int u = 0; u < 2; ++u) {
        int i = tid + u * 256;           // 0..511
        xi_row[u] = i >> 2;              // 0..127
        xi_kq[u]  = i & 3;               // 0..3
        wi_d[u]   = i >> 5;              // 0..15
        wi_t[u]   = (i >> 2) & 7;        // 0..7
        wi_cq[u]  = i & 3;               // 0..3
    }
    const int tw_t = tid >> 4;           // for tid<128
    const int tw_k = tid & 15;

#define LOAD_CHUNK(D0)                                                          \
    do {                                                                        \
        _Pragma("unroll")                                                       \
        for (int u = 0; u < 2; ++u) {                                           \
            px[u] = *(const float4*)&features[(size_t)(row0 + xi_row[u]) * DIM  \
                                              + (D0) + xi_kq[u] * 4];           \
            pw[u] = *(const float4*)&bottom_W[((size_t)wi_t[u] * DIM            \
                                              + (D0) + wi_d[u]) * NC            \
                                              + wi_cq[u] * 4];                  \
        }                                                                       \
        if (tid < 128) ptw = top_W[(size_t)tw_t * DIM + (D0) + tw_k];           \
    } while (0)

#define STORE_CHUNK()                                                           \
    do {                                                                        \
        _Pragma("unroll")                                                       \
        for (int u = 0; u < 2; ++u) {                                           \
            Xs[xi_kq[u] * 4 + 0][xi_row[u]] = px[u].x;                          \
            Xs[xi_kq[u] * 4 + 1][xi_row[u]] = px[u].y;                          \
            Xs[xi_kq[u] * 4 + 2][xi_row[u]] = px[u].z;                          \
            Xs[xi_kq[u] * 4 + 3][xi_row[u]] = px[u].w;                          \
            *(float4*)&Ws[wi_d[u]][wi_t[u] * 16 + wi_cq[u] * 4] = pw[u];        \
        }                                                                       \
        if (tid < 128) Wts[tw_k][tw_t] = ptw;                                   \
    } while (0)

    // prologue
    LOAD_CHUNK(0);
    STORE_CHUNK();
    __syncthreads();

    for (int ch = 0; ch < NCHUNK; ++ch) {
        if (ch + 1 < NCHUNK) LOAD_CHUNK((ch + 1) * KC);   // hide DRAM latency

#pragma unroll
        for (int k = 0; k < KC; ++k) {
            float4 xa = *(const float4*)&Xs[k][ty * 8];
            float4 xb = *(const float4*)&Xs[k][ty * 8 + 4];
            // weight column-pairs, native 64-bit loads from smem
            double2 wva = *(const double2*)&Ws[k][tx * 8];
            double2 wvb = *(const double2*)&Ws[k][tx * 8 + 4];
            unsigned long long w0 = __double_as_longlong(wva.x);
            unsigned long long w1 = __double_as_longlong(wva.y);
            unsigned long long w2 = __double_as_longlong(wvb.x);
            unsigned long long w3 = __double_as_longlong(wvb.y);

            float xs[8] = {xa.x, xa.y, xa.z, xa.w, xb.x, xb.y, xb.z, xb.w};
#pragma unroll
            for (int r = 0; r < 8; ++r) {
                unsigned long long xx = pack_dup(xs[r]);
                fma2(acc[r][0], xx, w0);
                fma2(acc[r][1], xx, w1);
                fma2(acc[r][2], xx, w2);
                fma2(acc[r][3], xx, w3);
            }
            if (tx < 8) {
                float wt = Wts[k][tx];
#pragma unroll
                for (int r = 0; r < 8; ++r) tacc[r] = fmaf(xs[r], wt, tacc[r]);
            }
        }
        __syncthreads();
        if (ch + 1 < NCHUNK) STORE_CHUNK();
        __syncthreads();
    }

    // write raw logits to scratch (biases applied in epilogue kernel)
#pragma unroll
    for (int r = 0; r < 8; ++r) {
        const int rowg = row0 + ty * 8 + r;
        float o[8];
#pragma unroll
        for (int c2 = 0; c2 < 4; ++c2) {
            o[2 * c2]     = lo32(acc[r][c2]);
            o[2 * c2 + 1] = hi32(acc[r][c2]);
        }
        float* Lrow = &g_logits[(size_t)rowg * NL];
        *(float4*)&Lrow[tx * 8]     = make_float4(o[0], o[1], o[2], o[3]);
        *(float4*)&Lrow[tx * 8 + 4] = make_float4(o[4], o[5], o[6], o[7]);
        if (tx < 8) Lrow[NB + tx] = tacc[r];
    }
#undef LOAD_CHUNK
#undef STORE_CHUNK
}

// ============================================================================
// Epilogue: one thread per (row, top-label): sigmoid(top) * softmax(bottom_16)
// ============================================================================
__global__ void __launch_bounds__(256)
hc_epilogue_kernel(const float* __restrict__ top_b,
                   const float* __restrict__ bottom_b,
                   float* __restrict__ out)
{
    const int g   = blockIdx.x * blockDim.x + threadIdx.x;   // 0 .. B*NTOP-1
    const int row = g >> 3;
    const int t   = g & 7;

    const float* Lrow = &g_logits[(size_t)row * NL];

    const float topl = Lrow[NB + t] + top_b[t];
    const float ts   = 1.0f / (1.0f + expf(-topl));

    float v[16];
#pragma unroll
    for (int q = 0; q < 4; ++q) {
        float4 a  = *(const float4*)&Lrow[t * 16 + q * 4];
        float4 bb = *(const float4*)&bottom_b[t * 16 + q * 4];
        v[q * 4 + 0] = a.x + bb.x;
        v[q * 4 + 1] = a.y + bb.y;
        v[q * 4 + 2] = a.z + bb.z;
        v[q * 4 + 3] = a.w + bb.w;
    }
    float m = v[0];
#pragma unroll
    for (int i = 1; i < 16; ++i) m = fmaxf(m, v[i]);
    float s = 0.0f;
#pragma unroll
    for (int i = 0; i < 16; ++i) { v[i] = expf(v[i] - m); s += v[i]; }
    const float scale = ts / s;

    float* orow = &out[(size_t)row * NB + t * 16];
#pragma unroll
    for (int q = 0; q < 4; ++q) {
        *(float4*)&orow[q * 4] = make_float4(v[q * 4 + 0] * scale,
                                             v[q * 4 + 1] * scale,
                                             v[q * 4 + 2] * scale,
                                             v[q * 4 + 3] * scale);
    }
}

// ============================================================================
// Launch: inputs in metadata order: features, top_W, top_b, bottom_W, bottom_b
// ============================================================================
extern "C" void kernel_launch(void* const* d_in, const int* in_sizes, int n_in,
                              void* d_out, int out_size)
{
    const float* features = (const float*)d_in[0];
    const float* top_W    = (const float*)d_in[1];
    const float* top_b    = (const float*)d_in[2];
    const float* bottom_W = (const float*)d_in[3];
    const float* bottom_b = (const float*)d_in[4];
    float* out = (float*)d_out;

    hc_gemm_kernel<<<B_ROWS / MT, 256>>>(features, top_W, bottom_W);
    hc_epilogue_kernel<<<(B_ROWS * NTOP) / 256, 256>>>(top_b, bottom_b, out);
}

// round 9
// speedup vs baseline: 3.2536x; 3.2536x over previous
#include <cuda_runtime.h>
#include <cuda_bf16.h>
#include <cstdint>
#include <cstring>

// ---------------- problem constants ----------------
#define B_ROWS  16384
#define DIM     2048
#define NTOP    8
#define NC      16
#define NB      128
#define NLOG    136
#define WROWS   144            // NLOG padded to 16-row multiple (pair tiles)
#define MT      128            // rows per CTA
#define KC      64             // K per chunk (64 bf16 = 128B data per row)
#define NCHUNK  (DIM / KC)     // 32

// smem: [0,1024) ctrl (biases), then two stages
#define CTRL_TOPB   16
#define CTRL_BOTB   512
#define SROW        144        // bytes per smem row (128 data + 16 pad)
#define A_HI_OFF    0                      // 128*144 = 18432
#define A_LO_OFF    18432
#define B_HI_OFF    36864                  // 144*144 = 20736
#define B_LO_OFF    57600
#define STAGE_BYTES 78336
#define SMEM_BYTES  (1024 + 2 * STAGE_BYTES)   // 157696
#define LSTR        148        // logits smem stride in floats (conflict-free)

// ---------------- static scratch: pre-split combined weights ----------------
__device__ __align__(16) __nv_bfloat16 g_Whi[WROWS * DIM];
__device__ __align__(16) __nv_bfloat16 g_Wlo[WROWS * DIM];

// ---------------- helpers ----------------
__device__ __forceinline__ uint32_t smem_u32(const void* p) {
    uint32_t a;
    asm("{ .reg .u64 t; cvta.to.shared.u64 t, %1; cvt.u32.u64 %0, t; }" : "=r"(a) : "l"(p));
    return a;
}
__device__ __forceinline__ void ldsm4(uint32_t r[4], uint32_t addr) {
    asm volatile("ldmatrix.sync.aligned.m8n8.x4.shared.b16 {%0,%1,%2,%3}, [%4];"
                 : "=r"(r[0]), "=r"(r[1]), "=r"(r[2]), "=r"(r[3]) : "r"(addr));
}
__device__ __forceinline__ void mma16816(float c[4], const uint32_t a[4],
                                         uint32_t b0, uint32_t b1) {
    asm volatile(
        "mma.sync.aligned.m16n8k16.row.col.f32.bf16.bf16.f32 "
        "{%0,%1,%2,%3}, {%4,%5,%6,%7}, {%8,%9}, {%0,%1,%2,%3};"
        : "+f"(c[0]), "+f"(c[1]), "+f"(c[2]), "+f"(c[3])
        : "r"(a[0]), "r"(a[1]), "r"(a[2]), "r"(a[3]), "r"(b0), "r"(b1));
}
__device__ __forceinline__ void cp16(uint32_t dst, const void* src) {
    asm volatile("cp.async.ca.shared.global [%0], [%1], 16;" :: "r"(dst), "l"(src) : "memory");
}
#define CP_COMMIT() asm volatile("cp.async.commit_group;" ::: "memory")
#define CP_WAIT0()  asm volatile("cp.async.wait_group 0;" ::: "memory")

__device__ __forceinline__ uint32_t packbf2(float a, float b) {
    __nv_bfloat162 t = __floats2bfloat162_rn(a, b);
    uint32_t u; memcpy(&u, &t, 4);
    return u;
}

// ---- inner compute: 4 k-steps of 3-term mma over one smem stage ----
// NP = B tile-pairs for this warp, NT = valid n8 tiles (NP=4,NT=8 | NP=5,NT=9)
template <int NP, int NT>
__device__ __forceinline__ void compute_chunk(float acc[2][9][4],
                                              uint32_t aHi, uint32_t aLo,
                                              uint32_t bHi, uint32_t bLo) {
#pragma unroll
    for (int k = 0; k < 4; ++k) {
        const uint32_t kb = (uint32_t)k * 32;   // k*16 elements * 2B
        uint32_t ah[2][4], al[2][4];
        ldsm4(ah[0], aHi + kb);
        ldsm4(ah[1], aHi + 16 * SROW + kb);
        ldsm4(al[0], aLo + kb);
        ldsm4(al[1], aLo + 16 * SROW + kb);
#pragma unroll
        for (int p = 0; p < NP; ++p) {
            uint32_t bh[4], bl[4];
            ldsm4(bh, bHi + p * 16 * SROW + kb);
            ldsm4(bl, bLo + p * 16 * SROW + kb);
#pragma unroll
            for (int mt = 0; mt < 2; ++mt) {
#pragma unroll
                for (int h = 0; h < 2; ++h) {
                    const int nt = 2 * p + h;
                    if (nt >= NT) continue;
                    mma16816(acc[mt][nt], ah[mt], bh[2 * h], bh[2 * h + 1]);
                    mma16816(acc[mt][nt], ah[mt], bl[2 * h], bl[2 * h + 1]);
                    mma16816(acc[mt][nt], al[mt], bh[2 * h], bh[2 * h + 1]);
                }
            }
        }
    }
}

// ============================================================================
// prep: combined [144][2048] weights, bf16 hi/lo split; rows >=136 zero
// ============================================================================
__global__ void hc_prep_kernel(const float* __restrict__ top_W,
                               const float* __restrict__ bottom_W) {
    int i = blockIdx.x * blockDim.x + threadIdx.x;
    if (i >= WROWS * DIM) return;
    int j = i / DIM, d = i % DIM;
    float w = 0.0f;
    if (j < NB)        w = bottom_W[((size_t)(j >> 4) * DIM + d) * NC + (j & 15)];
    else if (j < NLOG) w = top_W[(size_t)(j - NB) * DIM + d];
    __nv_bfloat16 h = __float2bfloat16_rn(w);
    g_Whi[(size_t)j * DIM + d] = h;
    g_Wlo[(size_t)j * DIM + d] = __float2bfloat16_rn(w - __bfloat162float(h));
}

// ============================================================================
// main: 3-term bf16 HMMA GEMM (M=128/CTA, N=136, K=2048) + fused epilogue
// ============================================================================
__global__ void __launch_bounds__(256, 1)
hc_gemm_kernel(const float* __restrict__ features,
               const float* __restrict__ top_b,
               const float* __restrict__ bottom_b,
               float* __restrict__ out) {
    extern __shared__ char smem[];
    const uint32_t smem_base = smem_u32(smem);
    const int tid  = threadIdx.x;
    const int lane = tid & 31;
    const int warp = tid >> 5;
    const int wm   = warp & 3;          // M group: rows wm*32..+31
    const int wn   = warp >> 2;         // N group: 0 -> cols 0..63, 1 -> 64..135
    const int row0 = blockIdx.x * MT;

    // stage biases
    if (tid < NB)  *(float*)(smem + CTRL_BOTB + tid * 4) = bottom_b[tid];
    if (tid >= NB && tid < NLOG)
        *(float*)(smem + CTRL_TOPB + (tid - NB) * 4) = top_b[tid - NB];

    // per-lane ldmatrix address patterns
    const int l7 = lane & 7;
    const int a_row  = lane & 15;                         // A x4 row offset
    const int a_kb   = (lane & 16) ? 16 : 0;              // A k-offset bytes
    const int b_row  = ((lane & 16) ? 8 : 0) + l7;        // B x4 row offset
    const int b_kb   = (lane & 8) ? 16 : 0;               // B k-offset bytes

    float acc[2][9][4];
#pragma unroll
    for (int mt = 0; mt < 2; ++mt)
#pragma unroll
        for (int nt = 0; nt < 9; ++nt)
#pragma unroll
            for (int i = 0; i < 4; ++i) acc[mt][nt][i] = 0.0f;

    float4 px[8];   // X register prefetch: 2048 float4 / 256 threads

    // ---- LDG X chunk into regs
#define LDG_X(D0)                                                              \
    do {                                                                       \
        _Pragma("unroll")                                                      \
        for (int u = 0; u < 8; ++u) {                                          \
            int idx = tid + u * 256;                                           \
            int r = idx >> 4, c4 = idx & 15;                                   \
            px[u] = *(const float4*)&features[(size_t)(row0 + r) * DIM + (D0)  \
                                              + c4 * 4];                       \
        }                                                                      \
    } while (0)

    // ---- split + STS X regs into stage
#define STS_X(STG)                                                             \
    do {                                                                       \
        char* sb = smem + 1024 + (STG) * STAGE_BYTES;                          \
        _Pragma("unroll")                                                      \
        for (int u = 0; u < 8; ++u) {                                          \
            int idx = tid + u * 256;                                           \
            int r = idx >> 4, c4 = idx & 15;                                   \
            uint32_t off = (uint32_t)(r * SROW + c4 * 8);                      \
            float4 v = px[u];                                                  \
            uint32_t h01 = packbf2(v.x, v.y);                                  \
            uint32_t h23 = packbf2(v.z, v.w);                                  \
            float fx = __uint_as_float(h01 << 16);                             \
            float fy = __uint_as_float(h01 & 0xffff0000u);                     \
            float fz = __uint_as_float(h23 << 16);                             \
            float fw = __uint_as_float(h23 & 0xffff0000u);                     \
            uint32_t l01 = packbf2(v.x - fx, v.y - fy);                        \
            uint32_t l23 = packbf2(v.z - fz, v.w - fw);                        \
            *(uint2*)(sb + A_HI_OFF + off) = make_uint2(h01, h23);             \
            *(uint2*)(sb + A_LO_OFF + off) = make_uint2(l01, l23);             \
        }                                                                      \
    } while (0)

    // ---- cp.async W chunk into stage
#define CP_W(D0, STG)                                                          \
    do {                                                                       \
        uint32_t sb = smem_base + 1024 + (STG) * STAGE_BYTES;                  \
        _Pragma("unroll")                                                      \
        for (int u = 0; u < 5; ++u) {                                          \
            int idx = tid + u * 256;                                           \
            if (idx < WROWS * 8) {                                             \
                int r = idx >> 3, g = idx & 7;                                 \
                uint32_t dst = sb + B_HI_OFF + (uint32_t)(r * SROW + g * 16);  \
                const size_t go = (size_t)r * DIM + (D0) + g * 8;              \
                cp16(dst, &g_Whi[go]);                                         \
                cp16(dst + (B_LO_OFF - B_HI_OFF), &g_Wlo[go]);                 \
            }                                                                  \
        }                                                                      \
        CP_COMMIT();                                                           \
    } while (0)

    // prologue: fill stage 0
    LDG_X(0);
    CP_W(0, 0);
    STS_X(0);
    CP_WAIT0();
    __syncthreads();

    for (int ch = 0; ch < NCHUNK; ++ch) {
        const int nxt = ch + 1;
        if (nxt < NCHUNK) {
            LDG_X(nxt * KC);
            CP_W(nxt * KC, nxt & 1);
        }

        const uint32_t sA = smem_base + 1024 + (uint32_t)(ch & 1) * STAGE_BYTES;
        const uint32_t aHi = sA + A_HI_OFF + (uint32_t)((wm * 32 + a_row) * SROW) + a_kb;
        const uint32_t aLo = aHi + (A_LO_OFF - A_HI_OFF);
        const uint32_t bHi = sA + B_HI_OFF + (uint32_t)((wn * 64 + b_row) * SROW) + b_kb;
        const uint32_t bLo = bHi + (B_LO_OFF - B_HI_OFF);

        if (wn == 0) compute_chunk<4, 8>(acc, aHi, aLo, bHi, bLo);
        else         compute_chunk<5, 9>(acc, aHi, aLo, bHi, bLo);

        if (nxt < NCHUNK) {
            STS_X(nxt & 1);
            CP_WAIT0();
        }
        __syncthreads();
    }
#undef LDG_X
#undef STS_X
#undef CP_W

    // ---- frags -> smem logits [128][LSTR] floats (reuse stage area)
    {
        float* Lf = (float*)(smem + 1024);
        const int rA = wm * 32 + (lane >> 2);
        const int cA = (lane & 3) * 2;
        const int NT = wn ? 9 : 8;
        for (int mt = 0; mt < 2; ++mt) {
#pragma unroll
            for (int nt = 0; nt < 9; ++nt) {
                if (nt >= NT) break;
                const int col = wn * 64 + nt * 8 + cA;
                const int r1 = rA + mt * 16;
                *(float2*)&Lf[r1 * LSTR + col]       = make_float2(acc[mt][nt][0], acc[mt][nt][1]);
                *(float2*)&Lf[(r1 + 8) * LSTR + col] = make_float2(acc[mt][nt][2], acc[mt][nt][3]);
            }
        }
    }
    __syncthreads();

    // ---- epilogue: 1024 (row, top) items over 256 threads
    {
        const float* Lf    = (const float*)(smem + 1024);
        const float* sm_tb = (const float*)(smem + CTRL_TOPB);
        const float* sm_bb = (const float*)(smem + CTRL_BOTB);
#pragma unroll
        for (int i = 0; i < 4; ++i) {
            const int item = tid + i * 256;
            const int r = item >> 3;     // local row
            const int t = item & 7;      // top label
            const float* Lr = &Lf[r * LSTR];

            const float tl = Lr[NB + t] + sm_tb[t];
            const float ts = 1.0f / (1.0f + __expf(-tl));

            float v[16];
            float m = -1e30f;
#pragma unroll
            for (int q = 0; q < 4; ++q) {
                float4 a = *(const float4*)&Lr[t * 16 + q * 4];
                v[q * 4 + 0] = a.x + sm_bb[t * 16 + q * 4 + 0];
                v[q * 4 + 1] = a.y + sm_bb[t * 16 + q * 4 + 1];
                v[q * 4 + 2] = a.z + sm_bb[t * 16 + q * 4 + 2];
                v[q * 4 + 3] = a.w + sm_bb[t * 16 + q * 4 + 3];
            }
#pragma unroll
            for (int j = 0; j < 16; ++j) m = fmaxf(m, v[j]);
            float s = 0.0f;
#pragma unroll
            for (int j = 0; j < 16; ++j) { v[j] = __expf(v[j] - m); s += v[j]; }
            const float sc = ts / s;

            float* orow = &out[(size_t)(row0 + r) * NB + t * 16];
#pragma unroll
            for (int q = 0; q < 4; ++q)
                *(float4*)&orow[q * 4] = make_float4(v[q * 4 + 0] * sc, v[q * 4 + 1] * sc,
                                                     v[q * 4 + 2] * sc, v[q * 4 + 3] * sc);
        }
    }
}

// ============================================================================
// launch: inputs: features, top_W, top_b, bottom_W, bottom_b
// ============================================================================
extern "C" void kernel_launch(void* const* d_in, const int* in_sizes, int n_in,
                              void* d_out, int out_size) {
    const float* features = (const float*)d_in[0];
    const float* top_W    = (const float*)d_in[1];
    const float* top_b    = (const float*)d_in[2];
    const float* bottom_W = (const float*)d_in[3];
    const float* bottom_b = (const float*)d_in[4];
    float* out = (float*)d_out;

    cudaFuncSetAttribute(hc_gemm_kernel,
                         cudaFuncAttributeMaxDynamicSharedMemorySize, SMEM_BYTES);

    hc_prep_kernel<<<(WROWS * DIM + 255) / 256, 256>>>(top_W, bottom_W);
    hc_gemm_kernel<<<B_ROWS / MT, 256, SMEM_BYTES>>>(features, top_b, bottom_b, out);
}

// round 10
// speedup vs baseline: 3.2630x; 1.0029x over previous
#include <cuda_runtime.h>
#include <cuda_bf16.h>
#include <cstdint>
#include <cstring>

// ---------------- problem constants ----------------
#define B_ROWS  16384
#define DIM     2048
#define NTOP    8
#define NC      16
#define NB      128
#define NLOG    136
#define WROWS   144            // NLOG padded to 16-row multiple (pair tiles)
#define MT      128            // rows per CTA
#define KC      64             // K per chunk (64 bf16 = 128B data per row)
#define NCHUNK  (DIM / KC)     // 32

// smem: [0,1024) ctrl (biases), then two stages
#define CTRL_TOPB   16
#define CTRL_BOTB   512
#define SROW        144        // bytes per smem row (128 data + 16 pad)
#define A_HI_OFF    0                      // 128*144 = 18432
#define A_LO_OFF    18432
#define B_HI_OFF    36864                  // 144*144 = 20736
#define B_LO_OFF    57600
#define STAGE_BYTES 78336
#define SMEM_BYTES  (1024 + 2 * STAGE_BYTES)   // 157696
#define LSTR        148        // logits smem stride in floats (conflict-free)

// ---------------- static scratch: pre-split combined weights ----------------
__device__ __align__(16) __nv_bfloat16 g_Whi[WROWS * DIM];
__device__ __align__(16) __nv_bfloat16 g_Wlo[WROWS * DIM];

// ---------------- helpers ----------------
__device__ __forceinline__ uint32_t smem_u32(const void* p) {
    uint32_t a;
    asm("{ .reg .u64 t; cvta.to.shared.u64 t, %1; cvt.u32.u64 %0, t; }" : "=r"(a) : "l"(p));
    return a;
}
__device__ __forceinline__ void ldsm4(uint32_t r[4], uint32_t addr) {
    asm volatile("ldmatrix.sync.aligned.m8n8.x4.shared.b16 {%0,%1,%2,%3}, [%4];"
                 : "=r"(r[0]), "=r"(r[1]), "=r"(r[2]), "=r"(r[3]) : "r"(addr));
}
__device__ __forceinline__ void mma16816(float c[4], const uint32_t a[4],
                                         uint32_t b0, uint32_t b1) {
    asm volatile(
        "mma.sync.aligned.m16n8k16.row.col.f32.bf16.bf16.f32 "
        "{%0,%1,%2,%3}, {%4,%5,%6,%7}, {%8,%9}, {%0,%1,%2,%3};"
        : "+f"(c[0]), "+f"(c[1]), "+f"(c[2]), "+f"(c[3])
        : "r"(a[0]), "r"(a[1]), "r"(a[2]), "r"(a[3]), "r"(b0), "r"(b1));
}
__device__ __forceinline__ void cp16(uint32_t dst, const void* src) {
    asm volatile("cp.async.ca.shared.global [%0], [%1], 16;" :: "r"(dst), "l"(src) : "memory");
}
#define CP_COMMIT() asm volatile("cp.async.commit_group;" ::: "memory")
#define CP_WAIT0()  asm volatile("cp.async.wait_group 0;" ::: "memory")

__device__ __forceinline__ uint32_t packbf2(float a, float b) {
    __nv_bfloat162 t = __floats2bfloat162_rn(a, b);
    uint32_t u; memcpy(&u, &t, 4);
    return u;
}

// ---- inner compute: 4 k-steps, term-major MMA order, frags preloaded per k ----
// NP = B tile-pairs for this warp, NT = valid n8 tiles (NP=4,NT=8 | NP=5,NT=9)
template <int NP, int NT>
__device__ __forceinline__ void compute_chunk(float acc[2][9][4],
                                              uint32_t aHi, uint32_t aLo,
                                              uint32_t bHi, uint32_t bLo) {
#pragma unroll
    for (int k = 0; k < 4; ++k) {
        const uint32_t kb = (uint32_t)k * 32;   // k*16 elements * 2B
        uint32_t ah[2][4], al[2][4];
        ldsm4(ah[0], aHi + kb);
        ldsm4(ah[1], aHi + 16 * SROW + kb);
        ldsm4(al[0], aLo + kb);
        ldsm4(al[1], aLo + 16 * SROW + kb);
        uint32_t bh[NP][4], bl[NP][4];
#pragma unroll
        for (int p = 0; p < NP; ++p) {
            ldsm4(bh[p], bHi + p * 16 * SROW + kb);
            ldsm4(bl[p], bLo + p * 16 * SROW + kb);
        }
        // term 1: Ah * Bh  (18 independent MMAs)
#pragma unroll
        for (int p = 0; p < NP; ++p)
#pragma unroll
            for (int h = 0; h < 2; ++h) {
                const int nt = 2 * p + h;
                if (nt >= NT) continue;
#pragma unroll
                for (int mt = 0; mt < 2; ++mt)
                    mma16816(acc[mt][nt], ah[mt], bh[p][2 * h], bh[p][2 * h + 1]);
            }
        // term 2: Ah * Bl
#pragma unroll
        for (int p = 0; p < NP; ++p)
#pragma unroll
            for (int h = 0; h < 2; ++h) {
                const int nt = 2 * p + h;
                if (nt >= NT) continue;
#pragma unroll
                for (int mt = 0; mt < 2; ++mt)
                    mma16816(acc[mt][nt], ah[mt], bl[p][2 * h], bl[p][2 * h + 1]);
            }
        // term 3: Al * Bh
#pragma unroll
        for (int p = 0; p < NP; ++p)
#pragma unroll
            for (int h = 0; h < 2; ++h) {
                const int nt = 2 * p + h;
                if (nt >= NT) continue;
#pragma unroll
                for (int mt = 0; mt < 2; ++mt)
                    mma16816(acc[mt][nt], al[mt], bh[p][2 * h], bh[p][2 * h + 1]);
            }
    }
}

// ============================================================================
// prep: combined [144][2048] weights, bf16 hi/lo split; rows >=136 zero
// ============================================================================
__global__ void hc_prep_kernel(const float* __restrict__ top_W,
                               const float* __restrict__ bottom_W) {
    int i = blockIdx.x * blockDim.x + threadIdx.x;
    if (i >= WROWS * DIM) return;
    int j = i / DIM, d = i % DIM;
    float w = 0.0f;
    if (j < NB)        w = bottom_W[((size_t)(j >> 4) * DIM + d) * NC + (j & 15)];
    else if (j < NLOG) w = top_W[(size_t)(j - NB) * DIM + d];
    __nv_bfloat16 h = __float2bfloat16_rn(w);
    g_Whi[(size_t)j * DIM + d] = h;
    g_Wlo[(size_t)j * DIM + d] = __float2bfloat16_rn(w - __bfloat162float(h));
}

// ============================================================================
// main: 3-term bf16 HMMA GEMM (M=128/CTA, N=136, K=2048) + fused epilogue
// ============================================================================
__global__ void __launch_bounds__(256, 1)
hc_gemm_kernel(const float* __restrict__ features,
               const float* __restrict__ top_b,
               const float* __restrict__ bottom_b,
               float* __restrict__ out) {
    extern __shared__ char smem[];
    const uint32_t smem_base = smem_u32(smem);
    const int tid  = threadIdx.x;
    const int lane = tid & 31;
    const int warp = tid >> 5;
    const int wm   = warp & 3;          // M group: rows wm*32..+31
    const int wn   = warp >> 2;         // N group: 0 -> cols 0..63, 1 -> 64..135
    const int row0 = blockIdx.x * MT;

    // stage biases
    if (tid < NB)  *(float*)(smem + CTRL_BOTB + tid * 4) = bottom_b[tid];
    if (tid >= NB && tid < NLOG)
        *(float*)(smem + CTRL_TOPB + (tid - NB) * 4) = top_b[tid - NB];

    // per-lane ldmatrix address patterns
    const int l7 = lane & 7;
    const int a_row  = lane & 15;                         // A x4 row offset
    const int a_kb   = (lane & 16) ? 16 : 0;              // A k-offset bytes
    const int b_row  = ((lane & 16) ? 8 : 0) + l7;        // B x4 row offset
    const int b_kb   = (lane & 8) ? 16 : 0;               // B k-offset bytes

    float acc[2][9][4];
#pragma unroll
    for (int mt = 0; mt < 2; ++mt)
#pragma unroll
        for (int nt = 0; nt < 9; ++nt)
#pragma unroll
            for (int i = 0; i < 4; ++i) acc[mt][nt][i] = 0.0f;

    float4 px[8];   // X register prefetch: 2048 float4 / 256 threads

    // ---- LDG X chunk into regs
#define LDG_X(D0)                                                              \
    do {                                                                       \
        _Pragma("unroll")                                                      \
        for (int u = 0; u < 8; ++u) {                                          \
            int idx = tid + u * 256;                                           \
            int r = idx >> 4, c4 = idx & 15;                                   \
            px[u] = *(const float4*)&features[(size_t)(row0 + r) * DIM + (D0)  \
                                              + c4 * 4];                       \
        }                                                                      \
    } while (0)

    // ---- split + STS X regs into stage
#define STS_X(STG)                                                             \
    do {                                                                       \
        char* sb = smem + 1024 + (STG) * STAGE_BYTES;                          \
        _Pragma("unroll")                                                      \
        for (int u = 0; u < 8; ++u) {                                          \
            int idx = tid + u * 256;                                           \
            int r = idx >> 4, c4 = idx & 15;                                   \
            uint32_t off = (uint32_t)(r * SROW + c4 * 8);                      \
            float4 v = px[u];                                                  \
            uint32_t h01 = packbf2(v.x, v.y);                                  \
            uint32_t h23 = packbf2(v.z, v.w);                                  \
            float fx = __uint_as_float(h01 << 16);                             \
            float fy = __uint_as_float(h01 & 0xffff0000u);                     \
            float fz = __uint_as_float(h23 << 16);                             \
            float fw = __uint_as_float(h23 & 0xffff0000u);                     \
            uint32_t l01 = packbf2(v.x - fx, v.y - fy);                        \
            uint32_t l23 = packbf2(v.z - fz, v.w - fw);                        \
            *(uint2*)(sb + A_HI_OFF + off) = make_uint2(h01, h23);             \
            *(uint2*)(sb + A_LO_OFF + off) = make_uint2(l01, l23);             \
        }                                                                      \
    } while (0)

    // ---- cp.async W chunk into stage
#define CP_W(D0, STG)                                                          \
    do {                                                                       \
        uint32_t sb = smem_base + 1024 + (STG) * STAGE_BYTES;                  \
        _Pragma("unroll")                                                      \
        for (int u = 0; u < 5; ++u) {                                          \
            int idx = tid + u * 256;                                           \
            if (idx < WROWS * 8) {                                             \
                int r = idx >> 3, g = idx & 7;                                 \
                uint32_t dst = sb + B_HI_OFF + (uint32_t)(r * SROW + g * 16);  \
                const size_t go = (size_t)r * DIM + (D0) + g * 8;              \
                cp16(dst, &g_Whi[go]);                                         \
                cp16(dst + (B_LO_OFF - B_HI_OFF), &g_Wlo[go]);                 \
            }                                                                  \
        }                                                                      \
        CP_COMMIT();                                                           \
    } while (0)

    // ---- prologue: fill stage 0; preload X for chunk 1 into regs
    LDG_X(0);
    CP_W(0, 0);
    STS_X(0);
    if (NCHUNK > 1) LDG_X(KC);
    CP_WAIT0();
    __syncthreads();

    // ---- main loop. At iter ch: px holds X(ch+1).
    //   1) cp.async W(ch+1) + STS X(ch+1) into free stage (no stall: px ready)
    //   2) LDG X(ch+2) into px (DRAM latency hidden under compute)
    //   3) compute(ch)  -- tensor pipe busy while cp.async streams in
    for (int ch = 0; ch < NCHUNK; ++ch) {
        const int nxt = ch + 1;
        if (nxt < NCHUNK) {
            CP_W(nxt * KC, nxt & 1);
            STS_X(nxt & 1);
            if (ch + 2 < NCHUNK) LDG_X((ch + 2) * KC);
        }

        const uint32_t sA = smem_base + 1024 + (uint32_t)(ch & 1) * STAGE_BYTES;
        const uint32_t aHi = sA + A_HI_OFF + (uint32_t)((wm * 32 + a_row) * SROW) + a_kb;
        const uint32_t aLo = aHi + (A_LO_OFF - A_HI_OFF);
        const uint32_t bHi = sA + B_HI_OFF + (uint32_t)((wn * 64 + b_row) * SROW) + b_kb;
        const uint32_t bLo = bHi + (B_LO_OFF - B_HI_OFF);

        if (wn == 0) compute_chunk<4, 8>(acc, aHi, aLo, bHi, bLo);
        else         compute_chunk<5, 9>(acc, aHi, aLo, bHi, bLo);

        CP_WAIT0();
        __syncthreads();
    }
#undef LDG_X
#undef STS_X
#undef CP_W

    // ---- frags -> smem logits [128][LSTR] floats (reuse stage area)
    {
        float* Lf = (float*)(smem + 1024);
        const int rA = wm * 32 + (lane >> 2);
        const int cA = (lane & 3) * 2;
        const int NT = wn ? 9 : 8;
        for (int mt = 0; mt < 2; ++mt) {
#pragma unroll
            for (int nt = 0; nt < 9; ++nt) {
                if (nt >= NT) break;
                const int col = wn * 64 + nt * 8 + cA;
                const int r1 = rA + mt * 16;
                *(float2*)&Lf[r1 * LSTR + col]       = make_float2(acc[mt][nt][0], acc[mt][nt][1]);
                *(float2*)&Lf[(r1 + 8) * LSTR + col] = make_float2(acc[mt][nt][2], acc[mt][nt][3]);
            }
        }
    }
    __syncthreads();

    // ---- epilogue: 1024 (row, top) items over 256 threads
    {
        const float* Lf    = (const float*)(smem + 1024);
        const float* sm_tb = (const float*)(smem + CTRL_TOPB);
        const float* sm_bb = (const float*)(smem + CTRL_BOTB);
#pragma unroll
        for (int i = 0; i < 4; ++i) {
            const int item = tid + i * 256;
            const int r = item >> 3;     // local row
            const int t = item & 7;      // top label
            const float* Lr = &Lf[r * LSTR];

            const float tl = Lr[NB + t] + sm_tb[t];
            const float ts = 1.0f / (1.0f + __expf(-tl));

            float v[16];
            float m = -1e30f;
#pragma unroll
            for (int q = 0; q < 4; ++q) {
                float4 a = *(const float4*)&Lr[t * 16 + q * 4];
                v[q * 4 + 0] = a.x + sm_bb[t * 16 + q * 4 + 0];
                v[q * 4 + 1] = a.y + sm_bb[t * 16 + q * 4 + 1];
                v[q * 4 + 2] = a.z + sm_bb[t * 16 + q * 4 + 2];
                v[q * 4 + 3] = a.w + sm_bb[t * 16 + q * 4 + 3];
            }
#pragma unroll
            for (int j = 0; j < 16; ++j) m = fmaxf(m, v[j]);
            float s = 0.0f;
#pragma unroll
            for (int j = 0; j < 16; ++j) { v[j] = __expf(v[j] - m); s += v[j]; }
            const float sc = ts / s;

            float* orow = &out[(size_t)(row0 + r) * NB + t * 16];
#pragma unroll
            for (int q = 0; q < 4; ++q)
                *(float4*)&orow[q * 4] = make_float4(v[q * 4 + 0] * sc, v[q * 4 + 1] * sc,
                                                     v[q * 4 + 2] * sc, v[q * 4 + 3] * sc);
        }
    }
}

// ============================================================================
// launch: inputs: features, top_W, top_b, bottom_W, bottom_b
// ============================================================================
extern "C" void kernel_launch(void* const* d_in, const int* in_sizes, int n_in,
                              void* d_out, int out_size) {
    const float* features = (const float*)d_in[0];
    const float* top_W    = (const float*)d_in[1];
    const float* top_b    = (const float*)d_in[2];
    const float* bottom_W = (const float*)d_in[3];
    const float* bottom_b = (const float*)d_in[4];
    float* out = (float*)d_out;

    cudaFuncSetAttribute(hc_gemm_kernel,
                         cudaFuncAttributeMaxDynamicSharedMemorySize, SMEM_BYTES);

    hc_prep_kernel<<<(WROWS * DIM + 255) / 256, 256>>>(top_W, bottom_W);
    hc_gemm_kernel<<<B_ROWS / MT, 256, SMEM_BYTES>>>(features, top_b, bottom_b, out);
}